// round 14
// baseline (speedup 1.0000x reference)
#include <cuda_runtime.h>
#include <cuda_fp16.h>

#define N_PTS   800000
#define B_SEG   16
#define PTS     50000
#define C_IN    32
#define C_HID   16
#define EPS_BN  1e-5f
#define EPS_NRM 1e-12f

#define TP      256                              // pass1 tile (points)
#define TPAD    257                              // padded point stride (words)

#define GRID1   444                              // 3 blocks/SM, 1 wave
#define CHUNK1  1802                             // 443*1802+1514 = 800000

#define BPS     55                               // pass2 blocks per segment
#define GRID2   (B_SEG * BPS)                    // 880 ≈ 6 blocks/SM
#define CHUNK2  910                              // 54*910+860 = 50000
#define TP2     256                              // pass2 tile (points)

// ---------------- device scratch (zero-init at load; self-reset each run) --
__device__ float    g_sum_h [C_HID];
__device__ float    g_sum_h2[C_HID];
__device__ float2   g_aff   [C_HID];             // (gamma/sigma, beta - m*gamma/sigma)
__device__ float    g_sum_a;
__device__ float    g_sum_a2;
__device__ float    g_seg_xa[B_SEG][C_IN];
__device__ float    g_seg_x [B_SEG][C_IN];
__device__ unsigned g_tick1, g_tick2;
__device__ uint4    g_h[N_PTS * 2];              // fp16 h: 16 halves/pt = 25.6MB

// Stage rows [ts, ts+tn) of x into TRANSPOSED smem sxT[c][p] (pad TPAD).
__device__ __forceinline__ void stage_tile(const float* __restrict__ x,
                                           float* sxT, int ts, int tn, int tid) {
    const float4* src = (const float4*)(x + (size_t)ts * C_IN);
    int nf = tn * 8;
    for (int f = tid; f < nf; f += 256) {
        float4 v = src[f];
        int row = f >> 3, q = f & 7;
        float* d = sxT + (q * 4) * TPAD + row;
        d[0]        = v.x;
        d[TPAD]     = v.y;
        d[2 * TPAD] = v.z;
        d[3 * TPAD] = v.w;
    }
}

// 8-channel FMA micro-step: unpack one uint4 of half2 W, accumulate.
__device__ __forceinline__ void dot8(const float* X, uint4 wv,
                                     float& s0, float& s1, float& s2, float& s3) {
    float2 f0 = __half22float2(*(__half2*)&wv.x);
    float2 f1 = __half22float2(*(__half2*)&wv.y);
    float2 f2 = __half22float2(*(__half2*)&wv.z);
    float2 f3 = __half22float2(*(__half2*)&wv.w);
    s0 = fmaf(X[0], f0.x, s0); s1 = fmaf(X[1], f0.y, s1);
    s2 = fmaf(X[2], f1.x, s2); s3 = fmaf(X[3], f1.y, s3);
    s0 = fmaf(X[4], f2.x, s0); s1 = fmaf(X[5], f2.y, s1);
    s2 = fmaf(X[6], f3.x, s2); s3 = fmaf(X[7], f3.y, s3);
}

// -------- pass1: GEMM (fp16 W) -> h (stats + fp16 store), BN1 (last block) -
__global__ void __launch_bounds__(256, 3)
pass1_kernel(const float* __restrict__ x,
             const float* __restrict__ W1,
             const float* __restrict__ b1,
             const float* __restrict__ gamma1,
             const float* __restrict__ beta1) {
    __shared__ float sxT[C_IN * TPAD];            // 32.9 KB
    __shared__ float hs[8][TP];                   // 8 KB
    __shared__ uint4 sWh[C_HID * 4];              // 1 KB: W1 as half2, 8 ch/uint4
    __shared__ float sb[C_HID];
    __shared__ bool  sLast;
    int tid  = threadIdx.x;
    int lane = tid & 31;
    int w    = tid >> 5;

    // convert W1 -> half2 (row-major pairing: half2 t = channels 2t,2t+1)
    {
        __half2 hv = __floats2half2_rn(W1[2 * tid], W1[2 * tid + 1]);
        ((unsigned*)sWh)[tid] = *(unsigned*)&hv;
    }
    if (tid < C_HID) sb[tid] = b1[tid];

    int start = blockIdx.x * CHUNK1;
    int end   = min(N_PTS, start + CHUNK1);

    float shA = 0.f, sh2A = 0.f, shB = 0.f, sh2B = 0.f;  // channels w, w+8
    __syncthreads();

    for (int ts = start; ts < end; ts += TP) {
        int tn = min(TP, end - ts);
        stage_tile(x, sxT, ts, tn, tid);
        __syncthreads();

        float X[32];
        if (tid < tn) {
#pragma unroll
            for (int c = 0; c < 32; c++) X[c] = sxT[c * TPAD + tid];
#pragma unroll 1
            for (int j = 0; j < 8; j++) {
                float s0 = 0.f, s1 = 0.f, s2 = 0.f, s3 = 0.f;
#pragma unroll
                for (int q4 = 0; q4 < 4; q4++)
                    dot8(X + 8 * q4, sWh[j * 4 + q4], s0, s1, s2, s3);
                hs[j][tid] = (s0 + s1) + (s2 + s3) + sb[j];
            }
        }
        __syncthreads();
        for (int p = lane; p < tn; p += 32) {     // stats, channel w
            float s = hs[w][p]; shA += s; sh2A = fmaf(s, s, sh2A);
        }
        if (tid < tn) {                            // pack h[0..7] -> fp16
            __half2 a0 = __floats2half2_rn(hs[0][tid], hs[1][tid]);
            __half2 a1 = __floats2half2_rn(hs[2][tid], hs[3][tid]);
            __half2 a2 = __floats2half2_rn(hs[4][tid], hs[5][tid]);
            __half2 a3 = __floats2half2_rn(hs[6][tid], hs[7][tid]);
            g_h[(size_t)(ts + tid) * 2] = make_uint4(
                *(unsigned*)&a0, *(unsigned*)&a1, *(unsigned*)&a2, *(unsigned*)&a3);
        }
        __syncthreads();                          // hs consumed
        if (tid < tn) {
#pragma unroll 1
            for (int j = 0; j < 8; j++) {
                float s0 = 0.f, s1 = 0.f, s2 = 0.f, s3 = 0.f;
#pragma unroll
                for (int q4 = 0; q4 < 4; q4++)
                    dot8(X + 8 * q4, sWh[(j + 8) * 4 + q4], s0, s1, s2, s3);
                hs[j][tid] = (s0 + s1) + (s2 + s3) + sb[j + 8];
            }
        }
        __syncthreads();
        for (int p = lane; p < tn; p += 32) {     // stats, channel w+8
            float s = hs[w][p]; shB += s; sh2B = fmaf(s, s, sh2B);
        }
        if (tid < tn) {                            // pack h[8..15] -> fp16
            __half2 a0 = __floats2half2_rn(hs[0][tid], hs[1][tid]);
            __half2 a1 = __floats2half2_rn(hs[2][tid], hs[3][tid]);
            __half2 a2 = __floats2half2_rn(hs[4][tid], hs[5][tid]);
            __half2 a3 = __floats2half2_rn(hs[6][tid], hs[7][tid]);
            g_h[(size_t)(ts + tid) * 2 + 1] = make_uint4(
                *(unsigned*)&a0, *(unsigned*)&a1, *(unsigned*)&a2, *(unsigned*)&a3);
        }
        __syncthreads();                          // before next staging
    }

    // warp butterfly (uniform, outside all loops)
#pragma unroll
    for (int o = 16; o > 0; o >>= 1) {
        shA  += __shfl_xor_sync(0xffffffffu, shA,  o);
        sh2A += __shfl_xor_sync(0xffffffffu, sh2A, o);
        shB  += __shfl_xor_sync(0xffffffffu, shB,  o);
        sh2B += __shfl_xor_sync(0xffffffffu, sh2B, o);
    }
    if (lane == 0) {
        atomicAdd(&g_sum_h [w],     shA);
        atomicAdd(&g_sum_h2[w],     sh2A);
        atomicAdd(&g_sum_h [w + 8], shB);
        atomicAdd(&g_sum_h2[w + 8], sh2B);
    }

    // ---- last block: BN1 affine coefficients; then self-reset scratch ----
    __threadfence();
    __syncthreads();
    if (tid == 0) sLast = (atomicAdd(&g_tick1, 1u) == (unsigned)(gridDim.x - 1));
    __syncthreads();
    if (sLast) {
        if (tid < C_HID) {
            float m   = g_sum_h [tid] * (1.f / N_PTS);
            float vv  = g_sum_h2[tid] * (1.f / N_PTS) - m * m;
            float inv = rsqrtf(vv + EPS_BN) * gamma1[tid];
            g_aff[tid] = make_float2(inv, beta1[tid] - m * inv);
            g_sum_h[tid] = 0.f; g_sum_h2[tid] = 0.f;
        }
        if (tid == 0) g_tick1 = 0u;
    }
}

// ---- pass2: a from stored fp16 h; direct-coalesced x accumulation ---------
__global__ void __launch_bounds__(256, 6)
pass2_kernel(const float* __restrict__ x,
             const float* __restrict__ W2,
             const float* __restrict__ b2,
             const float* __restrict__ gamma2,
             const float* __restrict__ beta2,
             const int*   __restrict__ length,
             float*       __restrict__ out) {
    __shared__ float2 saff[C_HID];
    __shared__ float  sw2[C_HID];
    __shared__ float  as_[TP2];
    __shared__ float  r_axa[8][C_IN];
    __shared__ float  r_ax [8][C_IN];
    __shared__ float  r_sa [8];
    __shared__ float  r_sa2[8];
    __shared__ bool   sLast;
    int tid  = threadIdx.x;
    int lane = tid & 31;
    int w    = tid >> 5;

    if (tid < C_HID) { saff[tid] = g_aff[tid]; sw2[tid] = W2[tid]; }
    float b20 = b2[0];

    int seg   = blockIdx.x / BPS;
    int blk   = blockIdx.x % BPS;
    int start = seg * PTS + blk * CHUNK2;
    int end   = min(seg * PTS + PTS, start + CHUNK2);

    float sa = 0.f, sa2 = 0.f, axa = 0.f, ax = 0.f;
    __syncthreads();

    for (int ts = start; ts < end; ts += TP2) {
        int tn = min(TP2, end - ts);
        if (tid < tn) {                            // thread = one point
            uint4 u0 = g_h[(size_t)(ts + tid) * 2];
            uint4 u1 = g_h[(size_t)(ts + tid) * 2 + 1];
            unsigned hw[8] = {u0.x, u0.y, u0.z, u0.w, u1.x, u1.y, u1.z, u1.w};
            float r = b20;
#pragma unroll
            for (int k = 0; k < 8; k++) {
                float2 f  = __half22float2(*(__half2*)&hw[k]);
                float2 A0 = saff[2 * k], A1 = saff[2 * k + 1];
                float s0 = fmaf(f.x, A0.x, A0.y);
                float s1 = fmaf(f.y, A1.x, A1.y);
                r = fmaf(fmaxf(s0, 0.f), sw2[2 * k],     r);
                r = fmaf(fmaxf(s1, 0.f), sw2[2 * k + 1], r);
            }
            as_[tid] = r;
            sa += r;
            sa2 = fmaf(r, r, sa2);
        }
        __syncthreads();

        // channel-split accumulation: warp w takes points w, w+8, ...
#pragma unroll 4
        for (int p = w; p < tn; p += 8) {
            float a  = as_[p];                     // smem broadcast
            float xv = x[(size_t)(ts + p) * C_IN + lane];  // coalesced LDG
            axa = fmaf(xv, a, axa);
            ax += xv;
        }
        __syncthreads();
    }

    // ---- block reduction + global atomics ----
    r_axa[w][lane] = axa;
    r_ax [w][lane] = ax;
#pragma unroll
    for (int o = 16; o > 0; o >>= 1) {             // uniform butterfly
        sa  += __shfl_xor_sync(0xffffffffu, sa,  o);
        sa2 += __shfl_xor_sync(0xffffffffu, sa2, o);
    }
    if (lane == 0) { r_sa[w] = sa; r_sa2[w] = sa2; }
    __syncthreads();
    if (tid < C_IN) {
        float A = 0.f, Xs = 0.f;
#pragma unroll
        for (int g = 0; g < 8; g++) { A += r_axa[g][tid]; Xs += r_ax[g][tid]; }
        atomicAdd(&g_seg_xa[seg][tid], A);
        atomicAdd(&g_seg_x [seg][tid], Xs);
    } else if (tid == C_IN) {
        float S = 0.f;
#pragma unroll
        for (int k = 0; k < 8; k++) S += r_sa[k];
        atomicAdd(&g_sum_a, S);
    } else if (tid == C_IN + 1) {
        float S = 0.f;
#pragma unroll
        for (int k = 0; k < 8; k++) S += r_sa2[k];
        atomicAdd(&g_sum_a2, S);
    }

    // ---- last block: BN2 affine + L2 normalize; then self-reset scratch ---
    __threadfence();
    __syncthreads();
    if (tid == 0) sLast = (atomicAdd(&g_tick2, 1u) == (unsigned)(gridDim.x - 1));
    __syncthreads();
    if (sLast) {
        float m     = g_sum_a  * (1.f / N_PTS);
        float v     = g_sum_a2 * (1.f / N_PTS) - m * m;
        float alpha = rsqrtf(v + EPS_BN) * gamma2[0];
        float betaC = beta2[0] - m * alpha;
#pragma unroll
        for (int half = 0; half < 2; half++) {
            int b = w + half * 8;
            float cnt = (float)length[b];
            float val = (alpha * g_seg_xa[b][lane] + betaC * g_seg_x[b][lane]) / cnt;
            float sq = val * val;
#pragma unroll
            for (int o = 16; o > 0; o >>= 1) sq += __shfl_xor_sync(0xffffffffu, sq, o);
            out[b * C_IN + lane] = val / fmaxf(sqrtf(sq), EPS_NRM);
        }
        __syncthreads();
        for (int i2 = tid; i2 < B_SEG * C_IN; i2 += 256) {
            ((float*)g_seg_xa)[i2] = 0.f;
            ((float*)g_seg_x )[i2] = 0.f;
        }
        if (tid == 0) { g_sum_a = 0.f; g_sum_a2 = 0.f; g_tick2 = 0u; }
    }
}

// ---------------------------------------------------------------- launch --
extern "C" void kernel_launch(void* const* d_in, const int* in_sizes, int n_in,
                              void* d_out, int out_size) {
    const float* x      = (const float*)d_in[0];
    const float* W1     = (const float*)d_in[1];
    const float* b1     = (const float*)d_in[2];
    const float* gamma1 = (const float*)d_in[3];
    const float* beta1  = (const float*)d_in[4];
    const float* W2     = (const float*)d_in[5];
    const float* b2     = (const float*)d_in[6];
    const float* gamma2 = (const float*)d_in[7];
    const float* beta2  = (const float*)d_in[8];
    const int* length   = (const int*)d_in[10];
    float* out          = (float*)d_out;

    pass1_kernel<<<GRID1, 256>>>(x, W1, b1, gamma1, beta1);
    pass2_kernel<<<GRID2, 256>>>(x, W2, b2, gamma2, beta2, length, out);
}

// round 17
// speedup vs baseline: 1.0668x; 1.0668x over previous
#include <cuda_runtime.h>
#include <cuda_fp16.h>

#define N_PTS   800000
#define B_SEG   16
#define PTS     50000
#define C_IN    32
#define C_HID   16
#define EPS_BN  1e-5f
#define EPS_NRM 1e-12f

#define TP      256                              // pass1 tile (points)
#define TPAD    257                              // padded point stride (words)

#define GRID1   296                              // 2 blocks/SM, 1 wave
#define CHUNK1  2704                             // even; 295*2704+2320 = 800000

#define BPS     55                               // pass2 blocks per segment
#define GRID2   (B_SEG * BPS)                    // 880 ≈ 6 blocks/SM
#define CHUNK2  910                              // 54*910+860 = 50000
#define TP2     256                              // pass2 tile (points)

// ---------------- device scratch (zero-init at load; self-reset each run) --
__device__ float    g_sum_h [C_HID];
__device__ float    g_sum_h2[C_HID];
__device__ float2   g_aff   [C_HID];             // (gamma/sigma, beta - m*gamma/sigma)
__device__ float    g_sum_a;
__device__ float    g_sum_a2;
__device__ float    g_seg_xa[B_SEG][C_IN];
__device__ float    g_seg_x [B_SEG][C_IN];
__device__ unsigned g_tick1, g_tick2;
__device__ uint4    g_h[N_PTS * 2];              // fp16 h: 16 halves/pt = 25.6MB

// Stage rows [ts, ts+tn) of x into TRANSPOSED smem sxT[c][p] (pad TPAD).
__device__ __forceinline__ void stage_tile(const float* __restrict__ x,
                                           float* sxT, int ts, int tn, int tid) {
    const float4* src = (const float4*)(x + (size_t)ts * C_IN);
    int nf = tn * 8;
    for (int f = tid; f < nf; f += 256) {
        float4 v = src[f];
        int row = f >> 3, q = f & 7;
        float* d = sxT + (q * 4) * TPAD + row;
        d[0]        = v.x;
        d[TPAD]     = v.y;
        d[2 * TPAD] = v.z;
        d[3 * TPAD] = v.w;
    }
}

// -------- pass1: GEMM (fp32 W, 2 pts/thread) -> h; BN1 coeffs (last block) -
__global__ void __launch_bounds__(256, 2)
pass1_kernel(const float* __restrict__ x,
             const float* __restrict__ W1,
             const float* __restrict__ b1,
             const float* __restrict__ gamma1,
             const float* __restrict__ beta1) {
    __shared__ float sxT[C_IN * TPAD];            // 32.9 KB
    __shared__ float hs[8][TP];                   // 8 KB
    __shared__ float sW[C_HID * C_IN];            // 2 KB (fp32 W)
    __shared__ float sb[C_HID];
    __shared__ bool  sLast;
    int tid  = threadIdx.x;
    int lane = tid & 31;
    int w    = tid >> 5;
    int p0   = 2 * tid;                           // this thread's two points
    int p1   = 2 * tid + 1;

    for (int i = tid; i < C_HID * C_IN; i += 256) sW[i] = W1[i];
    if (tid < C_HID) sb[tid] = b1[tid];

    int start = blockIdx.x * CHUNK1;
    int end   = min(N_PTS, start + CHUNK1);

    float shA = 0.f, sh2A = 0.f, shB = 0.f, sh2B = 0.f;  // channels w, w+8
    __syncthreads();

    for (int ts = start; ts < end; ts += TP) {
        int tn = min(TP, end - ts);               // always even
        stage_tile(x, sxT, ts, tn, tid);
        __syncthreads();

        float4 X0[8], X1[8];
        bool act = (p0 < tn);
        if (act) {
#pragma unroll
            for (int q = 0; q < 8; q++) {
                const float* c0 = sxT + (4 * q) * TPAD;
                X0[q] = make_float4(c0[p0], c0[TPAD + p0], c0[2*TPAD + p0], c0[3*TPAD + p0]);
                X1[q] = make_float4(c0[p1], c0[TPAD + p1], c0[2*TPAD + p1], c0[3*TPAD + p1]);
            }
#pragma unroll 1
            for (int j = 0; j < 8; j++) {         // W LDS.128 shared by 2 pts
                const float4* wr = (const float4*)(sW + j * C_IN);
                float a0 = 0.f, a1 = 0.f, b0 = 0.f, b1v = 0.f;
#pragma unroll
                for (int q = 0; q < 8; q += 2) {
                    float4 wv = wr[q], wu = wr[q + 1];
                    a0 = fmaf(X0[q].x, wv.x, a0); a0 = fmaf(X0[q].y, wv.y, a0);
                    a0 = fmaf(X0[q].z, wv.z, a0); a0 = fmaf(X0[q].w, wv.w, a0);
                    b0 = fmaf(X0[q+1].x, wu.x, b0); b0 = fmaf(X0[q+1].y, wu.y, b0);
                    b0 = fmaf(X0[q+1].z, wu.z, b0); b0 = fmaf(X0[q+1].w, wu.w, b0);
                    a1 = fmaf(X1[q].x, wv.x, a1); a1 = fmaf(X1[q].y, wv.y, a1);
                    a1 = fmaf(X1[q].z, wv.z, a1); a1 = fmaf(X1[q].w, wv.w, a1);
                    b1v = fmaf(X1[q+1].x, wu.x, b1v); b1v = fmaf(X1[q+1].y, wu.y, b1v);
                    b1v = fmaf(X1[q+1].z, wu.z, b1v); b1v = fmaf(X1[q+1].w, wu.w, b1v);
                }
                hs[j][p0] = a0 + b0 + sb[j];
                hs[j][p1] = a1 + b1v + sb[j];
            }
        }
        __syncthreads();
        for (int p = lane; p < tn; p += 32) {     // stats, channel w
            float s = hs[w][p]; shA += s; sh2A = fmaf(s, s, sh2A);
        }
        if (act) {                                 // pack h[0..7], both points
            __half2 c0 = __floats2half2_rn(hs[0][p0], hs[1][p0]);
            __half2 c1 = __floats2half2_rn(hs[2][p0], hs[3][p0]);
            __half2 c2 = __floats2half2_rn(hs[4][p0], hs[5][p0]);
            __half2 c3 = __floats2half2_rn(hs[6][p0], hs[7][p0]);
            g_h[(size_t)(ts + p0) * 2] = make_uint4(
                *(unsigned*)&c0, *(unsigned*)&c1, *(unsigned*)&c2, *(unsigned*)&c3);
            __half2 d0 = __floats2half2_rn(hs[0][p1], hs[1][p1]);
            __half2 d1 = __floats2half2_rn(hs[2][p1], hs[3][p1]);
            __half2 d2 = __floats2half2_rn(hs[4][p1], hs[5][p1]);
            __half2 d3 = __floats2half2_rn(hs[6][p1], hs[7][p1]);
            g_h[(size_t)(ts + p1) * 2] = make_uint4(
                *(unsigned*)&d0, *(unsigned*)&d1, *(unsigned*)&d2, *(unsigned*)&d3);
        }
        __syncthreads();                          // hs consumed
        if (act) {
#pragma unroll 1
            for (int j = 0; j < 8; j++) {
                const float4* wr = (const float4*)(sW + (j + 8) * C_IN);
                float a0 = 0.f, a1 = 0.f, b0 = 0.f, b1v = 0.f;
#pragma unroll
                for (int q = 0; q < 8; q += 2) {
                    float4 wv = wr[q], wu = wr[q + 1];
                    a0 = fmaf(X0[q].x, wv.x, a0); a0 = fmaf(X0[q].y, wv.y, a0);
                    a0 = fmaf(X0[q].z, wv.z, a0); a0 = fmaf(X0[q].w, wv.w, a0);
                    b0 = fmaf(X0[q+1].x, wu.x, b0); b0 = fmaf(X0[q+1].y, wu.y, b0);
                    b0 = fmaf(X0[q+1].z, wu.z, b0); b0 = fmaf(X0[q+1].w, wu.w, b0);
                    a1 = fmaf(X1[q].x, wv.x, a1); a1 = fmaf(X1[q].y, wv.y, a1);
                    a1 = fmaf(X1[q].z, wv.z, a1); a1 = fmaf(X1[q].w, wv.w, a1);
                    b1v = fmaf(X1[q+1].x, wu.x, b1v); b1v = fmaf(X1[q+1].y, wu.y, b1v);
                    b1v = fmaf(X1[q+1].z, wu.z, b1v); b1v = fmaf(X1[q+1].w, wu.w, b1v);
                }
                hs[j][p0] = a0 + b0 + sb[j + 8];
                hs[j][p1] = a1 + b1v + sb[j + 8];
            }
        }
        __syncthreads();
        for (int p = lane; p < tn; p += 32) {     // stats, channel w+8
            float s = hs[w][p]; shB += s; sh2B = fmaf(s, s, sh2B);
        }
        if (act) {                                 // pack h[8..15], both points
            __half2 c0 = __floats2half2_rn(hs[0][p0], hs[1][p0]);
            __half2 c1 = __floats2half2_rn(hs[2][p0], hs[3][p0]);
            __half2 c2 = __floats2half2_rn(hs[4][p0], hs[5][p0]);
            __half2 c3 = __floats2half2_rn(hs[6][p0], hs[7][p0]);
            g_h[(size_t)(ts + p0) * 2 + 1] = make_uint4(
                *(unsigned*)&c0, *(unsigned*)&c1, *(unsigned*)&c2, *(unsigned*)&c3);
            __half2 d0 = __floats2half2_rn(hs[0][p1], hs[1][p1]);
            __half2 d1 = __floats2half2_rn(hs[2][p1], hs[3][p1]);
            __half2 d2 = __floats2half2_rn(hs[4][p1], hs[5][p1]);
            __half2 d3 = __floats2half2_rn(hs[6][p1], hs[7][p1]);
            g_h[(size_t)(ts + p1) * 2 + 1] = make_uint4(
                *(unsigned*)&d0, *(unsigned*)&d1, *(unsigned*)&d2, *(unsigned*)&d3);
        }
        __syncthreads();                          // before next staging
    }

    // warp butterfly (uniform, outside all loops)
#pragma unroll
    for (int o = 16; o > 0; o >>= 1) {
        shA  += __shfl_xor_sync(0xffffffffu, shA,  o);
        sh2A += __shfl_xor_sync(0xffffffffu, sh2A, o);
        shB  += __shfl_xor_sync(0xffffffffu, shB,  o);
        sh2B += __shfl_xor_sync(0xffffffffu, sh2B, o);
    }
    if (lane == 0) {
        atomicAdd(&g_sum_h [w],     shA);
        atomicAdd(&g_sum_h2[w],     sh2A);
        atomicAdd(&g_sum_h [w + 8], shB);
        atomicAdd(&g_sum_h2[w + 8], sh2B);
    }

    // ---- last block: BN1 affine coefficients; then self-reset scratch ----
    __threadfence();
    __syncthreads();
    if (tid == 0) sLast = (atomicAdd(&g_tick1, 1u) == (unsigned)(gridDim.x - 1));
    __syncthreads();
    if (sLast) {
        if (tid < C_HID) {
            float m   = g_sum_h [tid] * (1.f / N_PTS);
            float vv  = g_sum_h2[tid] * (1.f / N_PTS) - m * m;
            float inv = rsqrtf(vv + EPS_BN) * gamma1[tid];
            g_aff[tid] = make_float2(inv, beta1[tid] - m * inv);
            g_sum_h[tid] = 0.f; g_sum_h2[tid] = 0.f;
        }
        if (tid == 0) g_tick1 = 0u;
    }
}

// ---- pass2: a from stored fp16 h; direct-coalesced x accumulation (R13) ---
__global__ void __launch_bounds__(256, 6)
pass2_kernel(const float* __restrict__ x,
             const float* __restrict__ W2,
             const float* __restrict__ b2,
             const float* __restrict__ gamma2,
             const float* __restrict__ beta2,
             const int*   __restrict__ length,
             float*       __restrict__ out) {
    __shared__ float2 saff[C_HID];
    __shared__ float  sw2[C_HID];
    __shared__ float  as_[TP2];
    __shared__ float  r_axa[8][C_IN];
    __shared__ float  r_ax [8][C_IN];
    __shared__ float  r_sa [8];
    __shared__ float  r_sa2[8];
    __shared__ bool   sLast;
    int tid  = threadIdx.x;
    int lane = tid & 31;
    int w    = tid >> 5;

    if (tid < C_HID) { saff[tid] = g_aff[tid]; sw2[tid] = W2[tid]; }
    float b20 = b2[0];

    int seg   = blockIdx.x / BPS;
    int blk   = blockIdx.x % BPS;
    int start = seg * PTS + blk * CHUNK2;
    int end   = min(seg * PTS + PTS, start + CHUNK2);

    float sa = 0.f, sa2 = 0.f, axa = 0.f, ax = 0.f;
    __syncthreads();

    for (int ts = start; ts < end; ts += TP2) {
        int tn = min(TP2, end - ts);
        if (tid < tn) {                            // thread = one point
            uint4 u0 = g_h[(size_t)(ts + tid) * 2];
            uint4 u1 = g_h[(size_t)(ts + tid) * 2 + 1];
            unsigned hw[8] = {u0.x, u0.y, u0.z, u0.w, u1.x, u1.y, u1.z, u1.w};
            float r = b20;
#pragma unroll
            for (int k = 0; k < 8; k++) {
                float2 f  = __half22float2(*(__half2*)&hw[k]);
                float2 A0 = saff[2 * k], A1 = saff[2 * k + 1];
                float s0 = fmaf(f.x, A0.x, A0.y);
                float s1 = fmaf(f.y, A1.x, A1.y);
                r = fmaf(fmaxf(s0, 0.f), sw2[2 * k],     r);
                r = fmaf(fmaxf(s1, 0.f), sw2[2 * k + 1], r);
            }
            as_[tid] = r;
            sa += r;
            sa2 = fmaf(r, r, sa2);
        }
        __syncthreads();

        // channel-split accumulation: warp w takes points w, w+8, ...
        for (int p = w; p < tn; p += 8) {
            float a  = as_[p];                     // smem broadcast
            float xv = x[(size_t)(ts + p) * C_IN + lane];  // coalesced LDG
            axa = fmaf(xv, a, axa);
            ax += xv;
        }
        __syncthreads();
    }

    // ---- block reduction + global atomics ----
    r_axa[w][lane] = axa;
    r_ax [w][lane] = ax;
#pragma unroll
    for (int o = 16; o > 0; o >>= 1) {             // uniform butterfly
        sa  += __shfl_xor_sync(0xffffffffu, sa,  o);
        sa2 += __shfl_xor_sync(0xffffffffu, sa2, o);
    }
    if (lane == 0) { r_sa[w] = sa; r_sa2[w] = sa2; }
    __syncthreads();
    if (tid < C_IN) {
        float A = 0.f, Xs = 0.f;
#pragma unroll
        for (int g = 0; g < 8; g++) { A += r_axa[g][tid]; Xs += r_ax[g][tid]; }
        atomicAdd(&g_seg_xa[seg][tid], A);
        atomicAdd(&g_seg_x [seg][tid], Xs);
    } else if (tid == C_IN) {
        float S = 0.f;
#pragma unroll
        for (int k = 0; k < 8; k++) S += r_sa[k];
        atomicAdd(&g_sum_a, S);
    } else if (tid == C_IN + 1) {
        float S = 0.f;
#pragma unroll
        for (int k = 0; k < 8; k++) S += r_sa2[k];
        atomicAdd(&g_sum_a2, S);
    }

    // ---- last block: BN2 affine + L2 normalize; then self-reset scratch ---
    __threadfence();
    __syncthreads();
    if (tid == 0) sLast = (atomicAdd(&g_tick2, 1u) == (unsigned)(gridDim.x - 1));
    __syncthreads();
    if (sLast) {
        float m     = g_sum_a  * (1.f / N_PTS);
        float v     = g_sum_a2 * (1.f / N_PTS) - m * m;
        float alpha = rsqrtf(v + EPS_BN) * gamma2[0];
        float betaC = beta2[0] - m * alpha;
#pragma unroll
        for (int half = 0; half < 2; half++) {
            int b = w + half * 8;
            float cnt = (float)length[b];
            float val = (alpha * g_seg_xa[b][lane] + betaC * g_seg_x[b][lane]) / cnt;
            float sq = val * val;
#pragma unroll
            for (int o = 16; o > 0; o >>= 1) sq += __shfl_xor_sync(0xffffffffu, sq, o);
            out[b * C_IN + lane] = val / fmaxf(sqrtf(sq), EPS_NRM);
        }
        __syncthreads();
        for (int i2 = tid; i2 < B_SEG * C_IN; i2 += 256) {
            ((float*)g_seg_xa)[i2] = 0.f;
            ((float*)g_seg_x )[i2] = 0.f;
        }
        if (tid == 0) { g_sum_a = 0.f; g_sum_a2 = 0.f; g_tick2 = 0u; }
    }
}

// ---------------------------------------------------------------- launch --
extern "C" void kernel_launch(void* const* d_in, const int* in_sizes, int n_in,
                              void* d_out, int out_size) {
    const float* x      = (const float*)d_in[0];
    const float* W1     = (const float*)d_in[1];
    const float* b1     = (const float*)d_in[2];
    const float* gamma1 = (const float*)d_in[3];
    const float* beta1  = (const float*)d_in[4];
    const float* W2     = (const float*)d_in[5];
    const float* b2     = (const float*)d_in[6];
    const float* gamma2 = (const float*)d_in[7];
    const float* beta2  = (const float*)d_in[8];
    const int* length   = (const int*)d_in[10];
    float* out          = (float*)d_out;

    pass1_kernel<<<GRID1, 256>>>(x, W1, b1, gamma1, beta1);
    pass2_kernel<<<GRID2, 256>>>(x, W2, b2, gamma2, beta2, length, out);
}